// round 10
// baseline (speedup 1.0000x reference)
#include <cuda_runtime.h>
#include <cuda_fp16.h>
#include <cstdint>
#include <math.h>

// ---------------- problem constants ----------------
#define Bn 4
#define Tn 200
#define Un 100
#define Dn 512
#define Vn 2048
#define EROWS (Bn * Tn)          // 800
#define PROWS (Bn * Un)          // 400
#define TUn   (Tn * Un)          // 20000
#define M_TOTAL (Bn * Tn * Un)   // 80000

#define M_TILE 128
#define N_TILE 128
#define KC     64
#define NKC    (Dn / KC)         // 8
#define NV_FULL (Vn / N_TILE)    // 16
#define JTHREADS 512

// tiles: 625 total; 592 full (4 waves of 148) + 33 split into 66 half-N CTAs
#define FULL_TILES 592
#define JGRID (FULL_TILES + 2 * (625 - FULL_TILES))   // 658

#define PAD 68

// A tile: fp16 [128 m][512 k], row stride 1040B (conflict-free ldmatrix)
#define ASTR 1040
#define A_BYTES (M_TILE * ASTR)            // 133120
// B tile: fp16 [128 n][64 k], row stride 144B, 4-slot ring
#define BSTR 144
#define BBUF (N_TILE * BSTR)               // 18432
#define JOINT_SMEM (A_BYTES + 4 * BBUF)    // 206848

// preamble grid split
#define ENC_BLKS 13
#define PRED_BLKS 7
#define PROJ_BLKS (ENC_BLKS + PRED_BLKS)   // 20
#define CONV_BLKS 64

// ---------------- global scratch ----------------
__device__ float g_e[EROWS * Dn];
__device__ float g_p[PROWS * Dn];
__device__ __half g_wh[Vn * Dn];

// ---------------- helpers ----------------
__device__ __forceinline__ uint32_t smem_to_u32(const void* p) {
    uint32_t a;
    asm("{ .reg .u64 t; cvta.to.shared.u64 t, %1; cvt.u32.u64 %0, t; }"
        : "=r"(a) : "l"(p));
    return a;
}

#define LDSM4(R, addr) \
    asm volatile("ldmatrix.sync.aligned.m8n8.x4.shared.b16 {%0,%1,%2,%3}, [%4];" \
        : "=r"((R)[0]), "=r"((R)[1]), "=r"((R)[2]), "=r"((R)[3]) : "r"(addr))

#define MMA16816(C, A, B0, B1) \
    asm volatile("mma.sync.aligned.m16n8k16.row.col.f32.f16.f16.f32 " \
        "{%0,%1,%2,%3}, {%4,%5,%6,%7}, {%8,%9}, {%0,%1,%2,%3};" \
        : "+f"((C)[0]), "+f"((C)[1]), "+f"((C)[2]), "+f"((C)[3]) \
        : "r"((A)[0]), "r"((A)[1]), "r"((A)[2]), "r"((A)[3]), "r"(B0), "r"(B1))

#define CP_ASYNC16(dst, src) \
    asm volatile("cp.async.cg.shared.global [%0], [%1], 16;" \
        :: "r"(dst), "l"(src) : "memory")
#define CP_COMMIT() asm volatile("cp.async.commit_group;" ::: "memory")
#define CP_WAIT1()  asm volatile("cp.async.wait_group 1;" ::: "memory")
#define CP_WAIT0()  asm volatile("cp.async.wait_group 0;" ::: "memory")

// ---------------------------------------------------------------------------
// Fused preamble: blocks [0,13) enc proj, [13,20) pred proj, rest: W convert
// ---------------------------------------------------------------------------
#define FMA16(ACC, AV, BV)                                        \
    ACC[0][0] += AV.x * BV.x; ACC[0][1] += AV.x * BV.y;           \
    ACC[0][2] += AV.x * BV.z; ACC[0][3] += AV.x * BV.w;           \
    ACC[1][0] += AV.y * BV.x; ACC[1][1] += AV.y * BV.y;           \
    ACC[1][2] += AV.y * BV.z; ACC[1][3] += AV.y * BV.w;           \
    ACC[2][0] += AV.z * BV.x; ACC[2][1] += AV.z * BV.y;           \
    ACC[2][2] += AV.z * BV.z; ACC[2][3] += AV.z * BV.w;           \
    ACC[3][0] += AV.w * BV.x; ACC[3][1] += AV.w * BV.y;           \
    ACC[3][2] += AV.w * BV.z; ACC[3][3] += AV.w * BV.w;

__global__ __launch_bounds__(256)
void preamble_kernel(const float* __restrict__ enc_out, const float* __restrict__ enc_w,
                     const float* __restrict__ enc_b,
                     const float* __restrict__ pred_out, const float* __restrict__ pred_w,
                     const float* __restrict__ pred_b,
                     const float* __restrict__ out_w,
                     float* __restrict__ ge, float* __restrict__ gp,
                     __half* __restrict__ wh)
{
    const int bx = blockIdx.x;
    const int tid = threadIdx.x;

    if (bx >= PROJ_BLKS) {
        int idx = (bx - PROJ_BLKS) * 8 + blockIdx.y;      // 0..511
        const float4* src = (const float4*)(out_w + (size_t)idx * 2048) + tid * 2;
        float4 f0 = src[0];
        float4 f1 = src[1];
        __half2 h0 = __floats2half2_rn(f0.x, f0.y);
        __half2 h1 = __floats2half2_rn(f0.z, f0.w);
        __half2 h2 = __floats2half2_rn(f1.x, f1.y);
        __half2 h3 = __floats2half2_rn(f1.z, f1.w);
        uint4 pkt;
        memcpy(&pkt.x, &h0, 4); memcpy(&pkt.y, &h1, 4);
        memcpy(&pkt.z, &h2, 4); memcpy(&pkt.w, &h3, 4);
        *((uint4*)(wh + (size_t)idx * 2048) + tid) = pkt;
        return;
    }

    const float* X;  const float* W;  const float* bias;  float* out;
    int rows, row0;
    if (bx < ENC_BLKS) { X = enc_out; W = enc_w;  bias = enc_b;  out = ge; rows = EROWS; row0 = bx * 64; }
    else               { X = pred_out; W = pred_w; bias = pred_b; out = gp; rows = PROWS; row0 = (bx - ENC_BLKS) * 64; }

    __shared__ float Xs[32][PAD];
    __shared__ float Ws[32][PAD];
    const int col0 = blockIdx.y * 64;
    const int tx = tid & 15;
    const int ty = tid >> 4;

    float acc[4][4] = {};

    for (int k0 = 0; k0 < Dn; k0 += 32) {
        __syncthreads();
#pragma unroll
        for (int i = 0; i < 8; i++) {
            int idx = tid + i * 256;
            int k = idx & 31;
            int r = idx >> 5;
            int row = row0 + r;
            Xs[k][r] = (row < rows) ? X[row * Dn + k0 + k] : 0.0f;
            Ws[k][r] = W[(col0 + r) * Dn + k0 + k];
        }
        __syncthreads();
#pragma unroll
        for (int k = 0; k < 32; k++) {
            float4 av = *(const float4*)&Xs[k][ty * 4];
            float4 bv = *(const float4*)&Ws[k][tx * 4];
            FMA16(acc, av, bv);
        }
    }

    float4 bs = *(const float4*)&bias[col0 + tx * 4];
#pragma unroll
    for (int i = 0; i < 4; i++) {
        int row = row0 + ty * 4 + i;
        if (row < rows) {
            float4 o;
            o.x = acc[i][0] + bs.x;
            o.y = acc[i][1] + bs.y;
            o.z = acc[i][2] + bs.z;
            o.w = acc[i][3] + bs.w;
            *(float4*)&out[row * Dn + col0 + tx * 4] = o;
        }
    }
}

// ---------------------------------------------------------------------------
// Joint: 512 threads, 16 warps (4m x 4n), warp tile 32x32, CTA tile 128x128.
// fp32-acc HMMA (R8 structure). Heterogeneous grid: bid < 592 -> full tile
// (all 16 v-tiles); bid >= 592 -> half tile (8 v-tiles) so the 5th wave is
// half-length, flattening the tail.
// ---------------------------------------------------------------------------
__global__ __launch_bounds__(JTHREADS, 1)
void joint_kernel(const __half* __restrict__ wh, const float* __restrict__ ob,
                  float* __restrict__ out)
{
    extern __shared__ char sm[];
    const uint32_t sA = smem_to_u32(sm);
    const uint32_t sB = sA + A_BYTES;

    const int tid  = threadIdx.x;
    const int lane = tid & 31;
    const int w    = tid >> 5;
    const int wm   = w & 3;          // warp m index 0..3
    const int wn   = w >> 2;         // warp n index 0..3
    const int m0w  = wm * 32;
    const int n0w  = wn * 32;

    // ---- heterogeneous tile mapping ----
    const int bid = blockIdx.x;
    int tileIdx, v0, nv;
    if (bid < FULL_TILES) { tileIdx = bid;                       v0 = 0;                 nv = NV_FULL; }
    else                  { tileIdx = FULL_TILES + ((bid - FULL_TILES) >> 1);
                            v0 = ((bid - FULL_TILES) & 1) * 8;   nv = 8; }
    const int m0 = tileIdx * M_TILE;
    const int nchunk = nv * NKC;

    // ---- Phase 1: A = tanh(e + p) -> fp16 SMEM tile ----
#pragma unroll 4
    for (int i = 0; i < 16; i++) {
        int q  = i * JTHREADS + tid; // 0..8191
        int r  = q >> 6;             // m row 0..127
        int kb = q & 63;             // 8-elem k block
        int m  = m0 + r;
        int b  = m / TUn;
        int rem = m - b * TUn;
        int t  = rem / Un;
        int u  = rem - t * Un;
        const float4* er = (const float4*)(g_e + (b * Tn + t) * Dn + kb * 8);
        const float4* pr = (const float4*)(g_p + (b * Un + u) * Dn + kb * 8);
        float4 e0 = er[0], p0 = pr[0];
        float4 e1 = er[1], p1 = pr[1];
        __half2 h0 = __floats2half2_rn(tanhf(e0.x + p0.x), tanhf(e0.y + p0.y));
        __half2 h1 = __floats2half2_rn(tanhf(e0.z + p0.z), tanhf(e0.w + p0.w));
        __half2 h2 = __floats2half2_rn(tanhf(e1.x + p1.x), tanhf(e1.y + p1.y));
        __half2 h3 = __floats2half2_rn(tanhf(e1.z + p1.z), tanhf(e1.w + p1.w));
        uint4 pkt;
        memcpy(&pkt.x, &h0, 4); memcpy(&pkt.y, &h1, 4);
        memcpy(&pkt.z, &h2, 4); memcpy(&pkt.w, &h3, 4);
        *(uint4*)(sm + r * ASTR + kb * 16) = pkt;
    }

    // ldmatrix lane address components
    const uint32_t aAddrBase = sA + (m0w + (lane & 15)) * ASTR + (lane >> 4) * 16;
    const int bN   = (lane & 7) + ((lane >> 4) & 1) * 8;
    const int bKof = ((lane >> 3) & 1) * 16;
    // cp.async per-thread coords (2 x 16B per chunk)
    const int cr0 = tid >> 3;            // row 0..63
    const int cs  = tid & 7;             // 16B slot within 64-k row

    float acc[2][4][4] = {};

    // prologue: prefetch chunk 0 (v=v0, kc=0) into slot 0
    {
        const __half* src = wh + (size_t)(v0 * N_TILE + cr0) * Dn + cs * 8;
#pragma unroll
        for (int j = 0; j < 2; j++) {
            CP_ASYNC16(sB + (cr0 + j * 64) * BSTR + cs * 16, src + (size_t)j * 64 * Dn);
        }
        CP_COMMIT();
    }

    for (int c = 0; c < nchunk; c++) {
        const int v  = v0 + (c >> 3);
        const int kc = c & 7;

        if (c + 1 < nchunk) {
            const int vn_ = v0 + ((c + 1) >> 3);
            const int kn_ = (c + 1) & 7;
            const uint32_t dst = sB + ((c + 1) & 3) * BBUF;
            const __half* src = wh + (size_t)(vn_ * N_TILE + cr0) * Dn + kn_ * KC + cs * 8;
#pragma unroll
            for (int j = 0; j < 2; j++) {
                CP_ASYNC16(dst + (cr0 + j * 64) * BSTR + cs * 16, src + (size_t)j * 64 * Dn);
            }
            CP_COMMIT();
            CP_WAIT1();
        } else {
            CP_WAIT0();
        }
        __syncthreads();

        const uint32_t sBbuf = sB + (c & 3) * BBUF;
        const uint32_t aChunk = aAddrBase + (uint32_t)(kc * KC) * 2;
        const uint32_t bBase0 = sBbuf + (uint32_t)(n0w + bN) * BSTR + (uint32_t)bKof;
        const uint32_t bBase1 = bBase0 + 16 * BSTR;

        // ---- software-pipelined fragment loads across ks ----
        uint32_t a[2][2][4], bf[2][2][4];
        LDSM4(a[0][0], aChunk);
        LDSM4(a[0][1], aChunk + 16 * ASTR);
        LDSM4(bf[0][0], bBase0);
        LDSM4(bf[0][1], bBase1);

#pragma unroll
        for (int ks = 0; ks < 4; ks++) {
            const int cur = ks & 1;
            const int nxt = cur ^ 1;
            if (ks < 3) {
                uint32_t kByte = (uint32_t)((ks + 1) * 16) * 2;
                LDSM4(a[nxt][0], aChunk + kByte);
                LDSM4(a[nxt][1], aChunk + kByte + 16 * ASTR);
                uint32_t kof = (uint32_t)((ks + 1) * 32);
                LDSM4(bf[nxt][0], bBase0 + kof);
                LDSM4(bf[nxt][1], bBase1 + kof);
            }
#pragma unroll
            for (int mi = 0; mi < 2; mi++) {
#pragma unroll
                for (int ni = 0; ni < 4; ni++) {
                    uint32_t b0 = bf[cur][ni >> 1][(ni & 1) * 2];
                    uint32_t b1 = bf[cur][ni >> 1][(ni & 1) * 2 + 1];
                    MMA16816(acc[mi][ni], a[cur][mi], b0, b1);
                }
            }
        }

        if (kc == 7) {
            // ---- epilogue for v-tile: bias + store, reset acc ----
#pragma unroll
            for (int mi = 0; mi < 2; mi++) {
                int gm = m0 + m0w + mi * 16 + (lane >> 2);
                float* orow0 = out + (size_t)gm * Vn + v * N_TILE;
                float* orow1 = orow0 + 8 * Vn;
#pragma unroll
                for (int ni = 0; ni < 4; ni++) {
                    int gn = n0w + ni * 8 + 2 * (lane & 3);
                    float2 bv = *(const float2*)(ob + v * N_TILE + gn);
                    float2 o0, o1;
                    o0.x = acc[mi][ni][0] + bv.x;
                    o0.y = acc[mi][ni][1] + bv.y;
                    o1.x = acc[mi][ni][2] + bv.x;
                    o1.y = acc[mi][ni][3] + bv.y;
                    *(float2*)(orow0 + gn) = o0;
                    *(float2*)(orow1 + gn) = o1;
#pragma unroll
                    for (int z = 0; z < 4; z++) acc[mi][ni][z] = 0.0f;
                }
            }
        }
    }
}

// ---------------------------------------------------------------------------
extern "C" void kernel_launch(void* const* d_in, const int* in_sizes, int n_in,
                              void* d_out, int out_size)
{
    const float* enc_out  = (const float*)d_in[0];
    const float* pred_out = (const float*)d_in[1];
    const float* enc_w    = (const float*)d_in[2];
    const float* enc_b    = (const float*)d_in[3];
    const float* pred_w   = (const float*)d_in[4];
    const float* pred_b   = (const float*)d_in[5];
    const float* out_w    = (const float*)d_in[6];
    const float* out_b    = (const float*)d_in[7];
    float* out = (float*)d_out;

    float *ge = nullptr, *gp = nullptr;
    __half* wh = nullptr;
    cudaGetSymbolAddress((void**)&ge, g_e);
    cudaGetSymbolAddress((void**)&gp, g_p);
    cudaGetSymbolAddress((void**)&wh, g_wh);

    preamble_kernel<<<dim3(PROJ_BLKS + CONV_BLKS, 8), 256>>>(
        enc_out, enc_w, enc_b, pred_out, pred_w, pred_b, out_w, ge, gp, wh);

    cudaFuncSetAttribute(joint_kernel,
                         cudaFuncAttributeMaxDynamicSharedMemorySize, JOINT_SMEM);
    joint_kernel<<<JGRID, JTHREADS, JOINT_SMEM>>>(wh, out_b, out);
}

// round 11
// speedup vs baseline: 1.5583x; 1.5583x over previous
#include <cuda_runtime.h>
#include <cuda_fp16.h>
#include <cstdint>
#include <math.h>

// ---------------- problem constants ----------------
#define Bn 4
#define Tn 200
#define Un 100
#define Dn 512
#define Vn 2048
#define EROWS (Bn * Tn)          // 800
#define PROWS (Bn * Un)          // 400
#define TUn   (Tn * Un)          // 20000
#define M_TOTAL (Bn * Tn * Un)   // 80000

#define M_TILE 128
#define N_TILE 128
#define KC     128
#define NKC    (Dn / KC)         // 4
#define NV     (Vn / N_TILE)     // 16
#define NCHUNK (NV * NKC)        // 64
#define JTHREADS 512

#define PAD 68

// A tile: fp16 [128 m][512 k] = 1024B rows, XOR-swizzled (no padding)
#define A_BYTES (M_TILE * 1024)            // 131072
// B tile: fp16 [128 n][128 k] = 256B rows, XOR-swizzled, 3-slot ring
#define BSTR 256
#define BBUF (N_TILE * BSTR)               // 32768
#define JOINT_SMEM (A_BYTES + 3 * BBUF)    // 229376 <= 232448

// preamble grid split
#define ENC_BLKS 13
#define PRED_BLKS 7
#define PROJ_BLKS (ENC_BLKS + PRED_BLKS)   // 20
#define CONV_BLKS 64

// ---------------- global scratch ----------------
__device__ float g_e[EROWS * Dn];
__device__ float g_p[PROWS * Dn];
__device__ __half g_wh[Vn * Dn];

// ---------------- helpers ----------------
__device__ __forceinline__ uint32_t smem_to_u32(const void* p) {
    uint32_t a;
    asm("{ .reg .u64 t; cvta.to.shared.u64 t, %1; cvt.u32.u64 %0, t; }"
        : "=r"(a) : "l"(p));
    return a;
}

#define LDSM4(R, addr) \
    asm volatile("ldmatrix.sync.aligned.m8n8.x4.shared.b16 {%0,%1,%2,%3}, [%4];" \
        : "=r"((R)[0]), "=r"((R)[1]), "=r"((R)[2]), "=r"((R)[3]) : "r"(addr))

#define MMA16816(C, A, B0, B1) \
    asm volatile("mma.sync.aligned.m16n8k16.row.col.f32.f16.f16.f32 " \
        "{%0,%1,%2,%3}, {%4,%5,%6,%7}, {%8,%9}, {%0,%1,%2,%3};" \
        : "+f"((C)[0]), "+f"((C)[1]), "+f"((C)[2]), "+f"((C)[3]) \
        : "r"((A)[0]), "r"((A)[1]), "r"((A)[2]), "r"((A)[3]), "r"(B0), "r"(B1))

#define CP_ASYNC16(dst, src) \
    asm volatile("cp.async.cg.shared.global [%0], [%1], 16;" \
        :: "r"(dst), "l"(src) : "memory")
#define CP_COMMIT() asm volatile("cp.async.commit_group;" ::: "memory")
#define CP_WAIT1()  asm volatile("cp.async.wait_group 1;" ::: "memory")
#define CP_WAIT0()  asm volatile("cp.async.wait_group 0;" ::: "memory")

// ---------------------------------------------------------------------------
// Fused preamble (unchanged, known-correct)
// ---------------------------------------------------------------------------
#define FMA16(ACC, AV, BV)                                        \
    ACC[0][0] += AV.x * BV.x; ACC[0][1] += AV.x * BV.y;           \
    ACC[0][2] += AV.x * BV.z; ACC[0][3] += AV.x * BV.w;           \
    ACC[1][0] += AV.y * BV.x; ACC[1][1] += AV.y * BV.y;           \
    ACC[1][2] += AV.y * BV.z; ACC[1][3] += AV.y * BV.w;           \
    ACC[2][0] += AV.z * BV.x; ACC[2][1] += AV.z * BV.y;           \
    ACC[2][2] += AV.z * BV.z; ACC[2][3] += AV.z * BV.w;           \
    ACC[3][0] += AV.w * BV.x; ACC[3][1] += AV.w * BV.y;           \
    ACC[3][2] += AV.w * BV.z; ACC[3][3] += AV.w * BV.w;

__global__ __launch_bounds__(256)
void preamble_kernel(const float* __restrict__ enc_out, const float* __restrict__ enc_w,
                     const float* __restrict__ enc_b,
                     const float* __restrict__ pred_out, const float* __restrict__ pred_w,
                     const float* __restrict__ pred_b,
                     const float* __restrict__ out_w,
                     float* __restrict__ ge, float* __restrict__ gp,
                     __half* __restrict__ wh)
{
    const int bx = blockIdx.x;
    const int tid = threadIdx.x;

    if (bx >= PROJ_BLKS) {
        int idx = (bx - PROJ_BLKS) * 8 + blockIdx.y;      // 0..511
        const float4* src = (const float4*)(out_w + (size_t)idx * 2048) + tid * 2;
        float4 f0 = src[0];
        float4 f1 = src[1];
        __half2 h0 = __floats2half2_rn(f0.x, f0.y);
        __half2 h1 = __floats2half2_rn(f0.z, f0.w);
        __half2 h2 = __floats2half2_rn(f1.x, f1.y);
        __half2 h3 = __floats2half2_rn(f1.z, f1.w);
        uint4 pkt;
        memcpy(&pkt.x, &h0, 4); memcpy(&pkt.y, &h1, 4);
        memcpy(&pkt.z, &h2, 4); memcpy(&pkt.w, &h3, 4);
        *((uint4*)(wh + (size_t)idx * 2048) + tid) = pkt;
        return;
    }

    const float* X;  const float* W;  const float* bias;  float* out;
    int rows, row0;
    if (bx < ENC_BLKS) { X = enc_out; W = enc_w;  bias = enc_b;  out = ge; rows = EROWS; row0 = bx * 64; }
    else               { X = pred_out; W = pred_w; bias = pred_b; out = gp; rows = PROWS; row0 = (bx - ENC_BLKS) * 64; }

    __shared__ float Xs[32][PAD];
    __shared__ float Ws[32][PAD];
    const int col0 = blockIdx.y * 64;
    const int tx = tid & 15;
    const int ty = tid >> 4;

    float acc[4][4] = {};

    for (int k0 = 0; k0 < Dn; k0 += 32) {
        __syncthreads();
#pragma unroll
        for (int i = 0; i < 8; i++) {
            int idx = tid + i * 256;
            int k = idx & 31;
            int r = idx >> 5;
            int row = row0 + r;
            Xs[k][r] = (row < rows) ? X[row * Dn + k0 + k] : 0.0f;
            Ws[k][r] = W[(col0 + r) * Dn + k0 + k];
        }
        __syncthreads();
#pragma unroll
        for (int k = 0; k < 32; k++) {
            float4 av = *(const float4*)&Xs[k][ty * 4];
            float4 bv = *(const float4*)&Ws[k][tx * 4];
            FMA16(acc, av, bv);
        }
    }

    float4 bs = *(const float4*)&bias[col0 + tx * 4];
#pragma unroll
    for (int i = 0; i < 4; i++) {
        int row = row0 + ty * 4 + i;
        if (row < rows) {
            float4 o;
            o.x = acc[i][0] + bs.x;
            o.y = acc[i][1] + bs.y;
            o.z = acc[i][2] + bs.z;
            o.w = acc[i][3] + bs.w;
            *(float4*)&out[row * Dn + col0 + tx * 4] = o;
        }
    }
}

// ---------------------------------------------------------------------------
// Joint: 512 threads, 16 warps (4m x 4n), warp tile 32x32, CTA tile 128x128.
// XOR-swizzled A (1024B rows) and B (256B rows), KC=128 -> 64 chunks total,
// 3-slot cp.async ring, one __syncthreads per 128-k chunk (barriers halved).
// ---------------------------------------------------------------------------
__global__ __launch_bounds__(JTHREADS, 1)
void joint_kernel(const __half* __restrict__ wh, const float* __restrict__ ob,
                  float* __restrict__ out)
{
    extern __shared__ char sm[];
    const uint32_t sA = smem_to_u32(sm);
    const uint32_t sB = sA + A_BYTES;

    const int tid  = threadIdx.x;
    const int lane = tid & 31;
    const int w    = tid >> 5;
    const int wm   = w & 3;          // warp m index 0..3
    const int wn   = w >> 2;         // warp n index 0..3
    const int m0w  = wm * 32;
    const int n0w  = wn * 32;
    const int m0   = blockIdx.x * M_TILE;

    // ---- Phase 1: A = tanh(e + p) -> fp16 swizzled SMEM tile ----
    // granule (16B) at (row r, granule kb) stored at r*1024 + ((kb ^ (r&7))<<4)
#pragma unroll 4
    for (int i = 0; i < 16; i++) {
        int q  = i * JTHREADS + tid; // 0..8191
        int r  = q >> 6;             // m row 0..127
        int kb = q & 63;             // granule 0..63
        int m  = m0 + r;
        int b  = m / TUn;
        int rem = m - b * TUn;
        int t  = rem / Un;
        int u  = rem - t * Un;
        const float4* er = (const float4*)(g_e + (b * Tn + t) * Dn + kb * 8);
        const float4* pr = (const float4*)(g_p + (b * Un + u) * Dn + kb * 8);
        float4 e0 = er[0], p0 = pr[0];
        float4 e1 = er[1], p1 = pr[1];
        __half2 h0 = __floats2half2_rn(tanhf(e0.x + p0.x), tanhf(e0.y + p0.y));
        __half2 h1 = __floats2half2_rn(tanhf(e0.z + p0.z), tanhf(e0.w + p0.w));
        __half2 h2 = __floats2half2_rn(tanhf(e1.x + p1.x), tanhf(e1.y + p1.y));
        __half2 h3 = __floats2half2_rn(tanhf(e1.z + p1.z), tanhf(e1.w + p1.w));
        uint4 pkt;
        memcpy(&pkt.x, &h0, 4); memcpy(&pkt.y, &h1, 4);
        memcpy(&pkt.z, &h2, 4); memcpy(&pkt.w, &h3, 4);
        *(uint4*)(sm + r * 1024 + ((kb ^ (r & 7)) << 4)) = pkt;
    }

    // ---- ldmatrix lane addressing (swizzled) ----
    // A: lane -> m row = m0w + (lane&15); k-granule select = lane>>4
    const int mL   = m0w + (lane & 15);
    const uint32_t aRow = sA + (uint32_t)mL * 1024;
    const int aXor = mL & 7;
    const int kSel = lane >> 4;                     // 0/1
    // B: lane -> n row in {bN, bN+16}; k-granule bit = (lane>>3)&1
    const int bN   = (lane & 7) + ((lane >> 4) & 1) * 8;
    const int kBit = (lane >> 3) & 1;
    const int nL0  = n0w + bN;
    const int nL1  = nL0 + 16;
    const int bXor0 = nL0 & 7;                      // == nL1 & 7
    // cp.async coords: 2048 granules/chunk, 4 per thread
    float acc[2][4][4] = {};

    // prologue: prefetch chunk 0 (v=0, kc=0) into slot 0
    {
#pragma unroll
        for (int j = 0; j < 4; j++) {
            int q = tid + j * JTHREADS;     // 0..2047
            int r = q >> 4, s = q & 15;
            CP_ASYNC16(sB + r * BSTR + ((s ^ (r & 7)) << 4),
                       wh + (size_t)r * Dn + s * 8);
        }
        CP_COMMIT();
    }

    int slotR = 0, slotW = 1;

    for (int c = 0; c < NCHUNK; c++) {
        const int v  = c >> 2;
        const int kc = c & 3;

        if (c + 1 < NCHUNK) {
            const int vn_ = (c + 1) >> 2;
            const int kn_ = (c + 1) & 3;
            const uint32_t dst = sB + (uint32_t)slotW * BBUF;
#pragma unroll
            for (int j = 0; j < 4; j++) {
                int q = tid + j * JTHREADS;
                int r = q >> 4, s = q & 15;
                CP_ASYNC16(dst + r * BSTR + ((s ^ (r & 7)) << 4),
                           wh + (size_t)(vn_ * N_TILE + r) * Dn + kn_ * KC + s * 8);
            }
            CP_COMMIT();
            CP_WAIT1();
        } else {
            CP_WAIT0();
        }
        __syncthreads();

        const uint32_t sBbuf = sB + (uint32_t)slotR * BBUF;
        const uint32_t bRow0 = sBbuf + (uint32_t)nL0 * BSTR;
        const uint32_t bRow1 = sBbuf + (uint32_t)nL1 * BSTR;
        const int kgA0 = kc * 16 + kSel;            // + ks*2 per step

        // ---- software-pipelined fragment loads across 8 ks-steps ----
        uint32_t a[2][2][4], bf[2][2][4];
        {
            int kgA = kgA0;
            LDSM4(a[0][0], aRow + ((kgA ^ aXor) << 4));
            LDSM4(a[0][1], aRow + 16 * 1024 + ((kgA ^ aXor) << 4));
            int kgB = kBit;
            LDSM4(bf[0][0], bRow0 + ((kgB ^ bXor0) << 4));
            LDSM4(bf[0][1], bRow1 + ((kgB ^ bXor0) << 4));
        }

#pragma unroll
        for (int ks = 0; ks < 8; ks++) {
            const int cur = ks & 1;
            const int nxt = cur ^ 1;
            if (ks < 7) {
                int kgA = kgA0 + (ks + 1) * 2;
                LDSM4(a[nxt][0], aRow + ((kgA ^ aXor) << 4));
                LDSM4(a[nxt][1], aRow + 16 * 1024 + ((kgA ^ aXor) << 4));
                int kgB = (ks + 1) * 2 + kBit;
                LDSM4(bf[nxt][0], bRow0 + ((kgB ^ bXor0) << 4));
                LDSM4(bf[nxt][1], bRow1 + ((kgB ^ bXor0) << 4));
            }
#pragma unroll
            for (int mi = 0; mi < 2; mi++) {
#pragma unroll
                for (int ni = 0; ni < 4; ni++) {
                    uint32_t b0 = bf[cur][ni >> 1][(ni & 1) * 2];
                    uint32_t b1 = bf[cur][ni >> 1][(ni & 1) * 2 + 1];
                    MMA16816(acc[mi][ni], a[cur][mi], b0, b1);
                }
            }
        }

        if (kc == 3) {
            // ---- epilogue for v-tile: bias + store, reset acc ----
#pragma unroll
            for (int mi = 0; mi < 2; mi++) {
                int gm = m0 + m0w + mi * 16 + (lane >> 2);
                float* orow0 = out + (size_t)gm * Vn + v * N_TILE;
                float* orow1 = orow0 + 8 * Vn;
#pragma unroll
                for (int ni = 0; ni < 4; ni++) {
                    int gn = n0w + ni * 8 + 2 * (lane & 3);
                    float2 bv = *(const float2*)(ob + v * N_TILE + gn);
                    float2 o0, o1;
                    o0.x = acc[mi][ni][0] + bv.x;
                    o0.y = acc[mi][ni][1] + bv.y;
                    o1.x = acc[mi][ni][2] + bv.x;
                    o1.y = acc[mi][ni][3] + bv.y;
                    *(float2*)(orow0 + gn) = o0;
                    *(float2*)(orow1 + gn) = o1;
#pragma unroll
                    for (int z = 0; z < 4; z++) acc[mi][ni][z] = 0.0f;
                }
            }
        }

        slotR = slotW;
        slotW = (slotW == 2) ? 0 : slotW + 1;
    }
}

// ---------------------------------------------------------------------------
extern "C" void kernel_launch(void* const* d_in, const int* in_sizes, int n_in,
                              void* d_out, int out_size)
{
    const float* enc_out  = (const float*)d_in[0];
    const float* pred_out = (const float*)d_in[1];
    const float* enc_w    = (const float*)d_in[2];
    const float* enc_b    = (const float*)d_in[3];
    const float* pred_w   = (const float*)d_in[4];
    const float* pred_b   = (const float*)d_in[5];
    const float* out_w    = (const float*)d_in[6];
    const float* out_b    = (const float*)d_in[7];
    float* out = (float*)d_out;

    float *ge = nullptr, *gp = nullptr;
    __half* wh = nullptr;
    cudaGetSymbolAddress((void**)&ge, g_e);
    cudaGetSymbolAddress((void**)&gp, g_p);
    cudaGetSymbolAddress((void**)&wh, g_wh);

    preamble_kernel<<<dim3(PROJ_BLKS + CONV_BLKS, 8), 256>>>(
        enc_out, enc_w, enc_b, pred_out, pred_w, pred_b, out_w, ge, gp, wh);

    cudaFuncSetAttribute(joint_kernel,
                         cudaFuncAttributeMaxDynamicSharedMemorySize, JOINT_SMEM);
    joint_kernel<<<M_TOTAL / M_TILE, JTHREADS, JOINT_SMEM>>>(wh, out_b, out);
}

// round 16
// speedup vs baseline: 1.5844x; 1.0167x over previous
#include <cuda_runtime.h>
#include <cuda_fp16.h>
#include <cstdint>
#include <math.h>

// ---------------- problem constants ----------------
#define Bn 4
#define Tn 200
#define Un 100
#define Dn 512
#define Vn 2048
#define EROWS (Bn * Tn)          // 800
#define PROWS (Bn * Un)          // 400
#define TUn   (Tn * Un)          // 20000
#define M_TOTAL (Bn * Tn * Un)   // 80000

#define M_TILE 128
#define N_TILE 128
#define KC     128
#define NKC    (Dn / KC)         // 4
#define NV     (Vn / N_TILE)     // 16
#define NCHUNK (NV * NKC)        // 64
#define JTHREADS 512

#define PAD 68

// A tile: fp16 [128 m][512 k] = 1024B rows, XOR-swizzled (no padding)
#define A_BYTES (M_TILE * 1024)            // 131072
// B tile: fp16 [128 n][128 k] = 256B rows, XOR-swizzled, 3-slot ring
#define BSTR 256
#define BBUF (N_TILE * BSTR)               // 32768
#define JOINT_SMEM (A_BYTES + 3 * BBUF)    // 229376 <= 232448

// preamble grid split: K-split x2 projections, then converts
#define ENC_BLKS 26                         // 13 row-tiles x 2 k-halves
#define PRED_BLKS 14                        // 7 row-tiles x 2 k-halves
#define PROJ_BLKS (ENC_BLKS + PRED_BLKS)   // 40
#define CONV_BLKS 64

// ---------------- global scratch ----------------
__device__ float g_e [EROWS * Dn];
__device__ float g_e2[EROWS * Dn];
__device__ float g_p [PROWS * Dn];
__device__ float g_p2[PROWS * Dn];
__device__ __half g_wh[Vn * Dn];

// ---------------- helpers ----------------
__device__ __forceinline__ uint32_t smem_to_u32(const void* p) {
    uint32_t a;
    asm("{ .reg .u64 t; cvta.to.shared.u64 t, %1; cvt.u32.u64 %0, t; }"
        : "=r"(a) : "l"(p));
    return a;
}

#define LDSM4(R, addr) \
    asm volatile("ldmatrix.sync.aligned.m8n8.x4.shared.b16 {%0,%1,%2,%3}, [%4];" \
        : "=r"((R)[0]), "=r"((R)[1]), "=r"((R)[2]), "=r"((R)[3]) : "r"(addr))

#define MMA16816(C, A, B0, B1) \
    asm volatile("mma.sync.aligned.m16n8k16.row.col.f32.f16.f16.f32 " \
        "{%0,%1,%2,%3}, {%4,%5,%6,%7}, {%8,%9}, {%0,%1,%2,%3};" \
        : "+f"((C)[0]), "+f"((C)[1]), "+f"((C)[2]), "+f"((C)[3]) \
        : "r"((A)[0]), "r"((A)[1]), "r"((A)[2]), "r"((A)[3]), "r"(B0), "r"(B1))

#define CP_ASYNC16(dst, src) \
    asm volatile("cp.async.cg.shared.global [%0], [%1], 16;" \
        :: "r"(dst), "l"(src) : "memory")
#define CP_COMMIT() asm volatile("cp.async.commit_group;" ::: "memory")
#define CP_WAIT1()  asm volatile("cp.async.wait_group 1;" ::: "memory")
#define CP_WAIT0()  asm volatile("cp.async.wait_group 0;" ::: "memory")

// ---------------------------------------------------------------------------
// Fused preamble: blocks [0,26) enc proj (x2 k-halves), [26,40) pred proj,
// [40,104) W convert. Proj computes a K=256 partial into g_X or g_X2.
// ---------------------------------------------------------------------------
#define FMA16(ACC, AV, BV)                                        \
    ACC[0][0] += AV.x * BV.x; ACC[0][1] += AV.x * BV.y;           \
    ACC[0][2] += AV.x * BV.z; ACC[0][3] += AV.x * BV.w;           \
    ACC[1][0] += AV.y * BV.x; ACC[1][1] += AV.y * BV.y;           \
    ACC[1][2] += AV.y * BV.z; ACC[1][3] += AV.y * BV.w;           \
    ACC[2][0] += AV.z * BV.x; ACC[2][1] += AV.z * BV.y;           \
    ACC[2][2] += AV.z * BV.z; ACC[2][3] += AV.z * BV.w;           \
    ACC[3][0] += AV.w * BV.x; ACC[3][1] += AV.w * BV.y;           \
    ACC[3][2] += AV.w * BV.z; ACC[3][3] += AV.w * BV.w;

__global__ __launch_bounds__(256)
void preamble_kernel(const float* __restrict__ enc_out, const float* __restrict__ enc_w,
                     const float* __restrict__ enc_b,
                     const float* __restrict__ pred_out, const float* __restrict__ pred_w,
                     const float* __restrict__ pred_b,
                     const float* __restrict__ out_w,
                     float* __restrict__ ge, float* __restrict__ ge2,
                     float* __restrict__ gp, float* __restrict__ gp2,
                     __half* __restrict__ wh)
{
    const int bx = blockIdx.x;
    const int tid = threadIdx.x;

    if (bx >= PROJ_BLKS) {
        int idx = (bx - PROJ_BLKS) * 8 + blockIdx.y;      // 0..511
        const float4* src = (const float4*)(out_w + (size_t)idx * 2048) + tid * 2;
        float4 f0 = src[0];
        float4 f1 = src[1];
        __half2 h0 = __floats2half2_rn(f0.x, f0.y);
        __half2 h1 = __floats2half2_rn(f0.z, f0.w);
        __half2 h2 = __floats2half2_rn(f1.x, f1.y);
        __half2 h3 = __floats2half2_rn(f1.z, f1.w);
        uint4 pkt;
        memcpy(&pkt.x, &h0, 4); memcpy(&pkt.y, &h1, 4);
        memcpy(&pkt.z, &h2, 4); memcpy(&pkt.w, &h3, 4);
        *((uint4*)(wh + (size_t)idx * 2048) + tid) = pkt;
        return;
    }

    // ---- projection partial: K-half kz of rows tile ----
    const float* X;  const float* W;  const float* bias;  float* out;
    int rows, row0, kz;
    if (bx < ENC_BLKS) {
        kz = bx & 1;  row0 = (bx >> 1) * 64;
        X = enc_out; W = enc_w;  bias = enc_b;
        out = kz ? ge2 : ge;  rows = EROWS;
    } else {
        int b2 = bx - ENC_BLKS;
        kz = b2 & 1;  row0 = (b2 >> 1) * 64;
        X = pred_out; W = pred_w; bias = pred_b;
        out = kz ? gp2 : gp;  rows = PROWS;
    }
    const int kbase = kz * 256;

    __shared__ float Xs[32][PAD];
    __shared__ float Ws[32][PAD];
    const int col0 = blockIdx.y * 64;
    const int tx = tid & 15;
    const int ty = tid >> 4;

    float acc[4][4] = {};

    for (int k0 = kbase; k0 < kbase + 256; k0 += 32) {
        __syncthreads();
#pragma unroll
        for (int i = 0; i < 8; i++) {
            int idx = tid + i * 256;
            int k = idx & 31;
            int r = idx >> 5;
            int row = row0 + r;
            Xs[k][r] = (row < rows) ? X[row * Dn + k0 + k] : 0.0f;
            Ws[k][r] = W[(col0 + r) * Dn + k0 + k];
        }
        __syncthreads();
#pragma unroll
        for (int k = 0; k < 32; k++) {
            float4 av = *(const float4*)&Xs[k][ty * 4];
            float4 bv = *(const float4*)&Ws[k][tx * 4];
            FMA16(acc, av, bv);
        }
    }

    // bias only in the kz==0 partial
    float4 bs = kz ? make_float4(0.f, 0.f, 0.f, 0.f)
                   : *(const float4*)&bias[col0 + tx * 4];
#pragma unroll
    for (int i = 0; i < 4; i++) {
        int row = row0 + ty * 4 + i;
        if (row < rows) {
            float4 o;
            o.x = acc[i][0] + bs.x;
            o.y = acc[i][1] + bs.y;
            o.z = acc[i][2] + bs.z;
            o.w = acc[i][3] + bs.w;
            *(float4*)&out[row * Dn + col0 + tx * 4] = o;
        }
    }
}

// ---------------------------------------------------------------------------
// Joint: 512 threads, 16 warps (4m x 4n), warp tile 32x32, CTA tile 128x128.
// XOR-swizzled A (1024B rows) and B (256B rows), KC=128 -> 64 chunks total,
// 3-slot cp.async ring, one __syncthreads per 128-k chunk.
// Phase-1 sums the two K-split projection partials.
// ---------------------------------------------------------------------------
__global__ __launch_bounds__(JTHREADS, 1)
void joint_kernel(const __half* __restrict__ wh, const float* __restrict__ ob,
                  float* __restrict__ out)
{
    extern __shared__ char sm[];
    const uint32_t sA = smem_to_u32(sm);
    const uint32_t sB = sA + A_BYTES;

    const int tid  = threadIdx.x;
    const int lane = tid & 31;
    const int w    = tid >> 5;
    const int wm   = w & 3;          // warp m index 0..3
    const int wn   = w >> 2;         // warp n index 0..3
    const int m0w  = wm * 32;
    const int n0w  = wn * 32;
    const int m0   = blockIdx.x * M_TILE;

    // ---- Phase 1: A = tanh(e + e2 + p + p2) -> fp16 swizzled SMEM tile ----
#pragma unroll 4
    for (int i = 0; i < 16; i++) {
        int q  = i * JTHREADS + tid; // 0..8191
        int r  = q >> 6;             // m row 0..127
        int kb = q & 63;             // granule 0..63
        int m  = m0 + r;
        int b  = m / TUn;
        int rem = m - b * TUn;
        int t  = rem / Un;
        int u  = rem - t * Un;
        size_t eoff = (size_t)(b * Tn + t) * Dn + kb * 8;
        size_t poff = (size_t)(b * Un + u) * Dn + kb * 8;
        const float4* er  = (const float4*)(g_e  + eoff);
        const float4* er2 = (const float4*)(g_e2 + eoff);
        const float4* pr  = (const float4*)(g_p  + poff);
        const float4* pr2 = (const float4*)(g_p2 + poff);
        float4 e0 = er[0],  e0b = er2[0], p0 = pr[0], p0b = pr2[0];
        float4 e1 = er[1],  e1b = er2[1], p1 = pr[1], p1b = pr2[1];
        float s0x = (e0.x + e0b.x) + (p0.x + p0b.x);
        float s0y = (e0.y + e0b.y) + (p0.y + p0b.y);
        float s0z = (e0.z + e0b.z) + (p0.z + p0b.z);
        float s0w = (e0.w + e0b.w) + (p0.w + p0b.w);
        float s1x = (e1.x + e1b.x) + (p1.x + p1b.x);
        float s1y = (e1.y + e1b.y) + (p1.y + p1b.y);
        float s1z = (e1.z + e1b.z) + (p1.z + p1b.z);
        float s1w = (e1.w + e1b.w) + (p1.w + p1b.w);
        __half2 h0 = __floats2half2_rn(tanhf(s0x), tanhf(s0y));
        __half2 h1 = __floats2half2_rn(tanhf(s0z), tanhf(s0w));
        __half2 h2 = __floats2half2_rn(tanhf(s1x), tanhf(s1y));
        __half2 h3 = __floats2half2_rn(tanhf(s1z), tanhf(s1w));
        uint4 pkt;
        memcpy(&pkt.x, &h0, 4); memcpy(&pkt.y, &h1, 4);
        memcpy(&pkt.z, &h2, 4); memcpy(&pkt.w, &h3, 4);
        *(uint4*)(sm + r * 1024 + ((kb ^ (r & 7)) << 4)) = pkt;
    }

    // ---- ldmatrix lane addressing (swizzled) ----
    const int mL   = m0w + (lane & 15);
    const uint32_t aRow = sA + (uint32_t)mL * 1024;
    const int aXor = mL & 7;
    const int kSel = lane >> 4;                     // 0/1
    const int bN   = (lane & 7) + ((lane >> 4) & 1) * 8;
    const int kBit = (lane >> 3) & 1;
    const int nL0  = n0w + bN;
    const int nL1  = nL0 + 16;
    const int bXor0 = nL0 & 7;
    float acc[2][4][4] = {};

    // prologue: prefetch chunk 0 (v=0, kc=0) into slot 0
    {
#pragma unroll
        for (int j = 0; j < 4; j++) {
            int q = tid + j * JTHREADS;     // 0..2047
            int r = q >> 4, s = q & 15;
            CP_ASYNC16(sB + r * BSTR + ((s ^ (r & 7)) << 4),
                       wh + (size_t)r * Dn + s * 8);
        }
        CP_COMMIT();
    }

    int slotR = 0, slotW = 1;

    for (int c = 0; c < NCHUNK; c++) {
        const int v  = c >> 2;
        const int kc = c & 3;

        if (c + 1 < NCHUNK) {
            const int vn_ = (c + 1) >> 2;
            const int kn_ = (c + 1) & 3;
            const uint32_t dst = sB + (uint32_t)slotW * BBUF;
#pragma unroll
            for (int j = 0; j < 4; j++) {
                int q = tid + j * JTHREADS;
                int r = q >> 4, s = q & 15;
                CP_ASYNC16(dst + r * BSTR + ((s ^ (r & 7)) << 4),
                           wh + (size_t)(vn_ * N_TILE + r) * Dn + kn_ * KC + s * 8);
            }
            CP_COMMIT();
            CP_WAIT1();
        } else {
            CP_WAIT0();
        }
        __syncthreads();

        const uint32_t sBbuf = sB + (uint32_t)slotR * BBUF;
        const uint32_t bRow0 = sBbuf + (uint32_t)nL0 * BSTR;
        const uint32_t bRow1 = sBbuf + (uint32_t)nL1 * BSTR;
        const int kgA0 = kc * 16 + kSel;

        // ---- software-pipelined fragment loads across 8 ks-steps ----
        uint32_t a[2][2][4], bf[2][2][4];
        {
            int kgA = kgA0;
            LDSM4(a[0][0], aRow + ((kgA ^ aXor) << 4));
            LDSM4(a[0][1], aRow + 16 * 1024 + ((kgA ^ aXor) << 4));
            int kgB = kBit;
            LDSM4(bf[0][0], bRow0 + ((kgB ^ bXor0) << 4));
            LDSM4(bf[0][1], bRow1 + ((kgB ^ bXor0) << 4));
        }

#pragma unroll
        for (int ks = 0; ks < 8; ks++) {
            const int cur = ks & 1;
            const int nxt = cur ^ 1;
            if (ks < 7) {
                int kgA = kgA0 + (ks + 1) * 2;
                LDSM4(a[nxt][0], aRow + ((kgA ^ aXor) << 4));
                LDSM4(a[nxt][1], aRow + 16 * 1024 + ((kgA ^ aXor) << 4));
                int kgB = (ks + 1) * 2 + kBit;
                LDSM4(bf[nxt][0], bRow0 + ((kgB ^ bXor0) << 4));
                LDSM4(bf[nxt][1], bRow1 + ((kgB ^ bXor0) << 4));
            }
#pragma unroll
            for (int mi = 0; mi < 2; mi++) {
#pragma unroll
                for (int ni = 0; ni < 4; ni++) {
                    uint32_t b0 = bf[cur][ni >> 1][(ni & 1) * 2];
                    uint32_t b1 = bf[cur][ni >> 1][(ni & 1) * 2 + 1];
                    MMA16816(acc[mi][ni], a[cur][mi], b0, b1);
                }
            }
        }

        if (kc == 3) {
            // ---- epilogue for v-tile: bias + store, reset acc ----
#pragma unroll
            for (int mi = 0; mi < 2; mi++) {
                int gm = m0 + m0w + mi * 16 + (lane >> 2);
                float* orow0 = out + (size_t)gm * Vn + v * N_TILE;
                float* orow1 = orow0 + 8 * Vn;
#pragma unroll
                for (int ni = 0; ni < 4; ni++) {
                    int gn = n0w + ni * 8 + 2 * (lane & 3);
                    float2 bv = *(const float2*)(ob + v * N_TILE + gn);
                    float2 o0, o1;
                    o0.x = acc[mi][ni][0] + bv.x;
                    o0.y = acc[mi][ni][1] + bv.y;
                    o1.x = acc[mi][ni][2] + bv.x;
                    o1.y = acc[mi][ni][3] + bv.y;
                    *(float2*)(orow0 + gn) = o0;
                    *(float2*)(orow1 + gn) = o1;
#pragma unroll
                    for (int z = 0; z < 4; z++) acc[mi][ni][z] = 0.0f;
                }
            }
        }

        slotR = slotW;
        slotW = (slotW == 2) ? 0 : slotW + 1;
    }
}

// ---------------------------------------------------------------------------
extern "C" void kernel_launch(void* const* d_in, const int* in_sizes, int n_in,
                              void* d_out, int out_size)
{
    const float* enc_out  = (const float*)d_in[0];
    const float* pred_out = (const float*)d_in[1];
    const float* enc_w    = (const float*)d_in[2];
    const float* enc_b    = (const float*)d_in[3];
    const float* pred_w   = (const float*)d_in[4];
    const float* pred_b   = (const float*)d_in[5];
    const float* out_w    = (const float*)d_in[6];
    const float* out_b    = (const float*)d_in[7];
    float* out = (float*)d_out;

    float *ge = nullptr, *ge2 = nullptr, *gp = nullptr, *gp2 = nullptr;
    __half* wh = nullptr;
    cudaGetSymbolAddress((void**)&ge,  g_e);
    cudaGetSymbolAddress((void**)&ge2, g_e2);
    cudaGetSymbolAddress((void**)&gp,  g_p);
    cudaGetSymbolAddress((void**)&gp2, g_p2);
    cudaGetSymbolAddress((void**)&wh,  g_wh);

    preamble_kernel<<<dim3(PROJ_BLKS + CONV_BLKS, 8), 256>>>(
        enc_out, enc_w, enc_b, pred_out, pred_w, pred_b, out_w,
        ge, ge2, gp, gp2, wh);

    cudaFuncSetAttribute(joint_kernel,
                         cudaFuncAttributeMaxDynamicSharedMemorySize, JOINT_SMEM);
    joint_kernel<<<M_TOTAL / M_TILE, JTHREADS, JOINT_SMEM>>>(wh, out_b, out);
}